// round 16
// baseline (speedup 1.0000x reference)
#include <cuda_runtime.h>
#include <math.h>

#define B_   8
#define T_   22050
#define NCH  31
#define BN   (B_*NCH)
#define M_   12
#define LG   2048
#define LH   512
#define EST  22056   // padded env row stride (floats); 16B-aligned rows
#define AST  22052   // padded adapt-out row stride; 16B-aligned rows
#define CH   8       // mod time chunks
#define CL   2757    // chunk length (8*2757 >= T_)
#define BNM  (BN*M_)
#define CTILE 2048   // conv_gt_ihc outputs per block
#define CHKS 44      // adapt samples per superstep chunk
#define NCHK 502     // ceil(22050/44)
#define NSS  (NCHK + 4)

// ---------------- device scratch (static, no runtime alloc) ----------------
__device__ float g_hpme[1024];
__device__ float g_wlp[256];
__device__ int   g_keff[NCH];
__device__ float g_y1[B_*T_];
__device__ __align__(16) float g_env[BN*EST + 64];
__device__ __align__(16) float g_ad[BN*AST + 64];
__device__ float g_msre[BNM*CH], g_msim[BNM*CH];
__device__ float g_Sre[BNM*CH],  g_Sim[BNM*CH];

// ---------------- prep_a: hpme only (launch 0) ----------------
__global__ void prep_a_kernel(const float* __restrict__ hp, const float* __restrict__ me) {
    int j = threadIdx.x;
    float s = 0.f;
    if (j < 1023) {
        int mlo = j - 511; if (mlo < 0) mlo = 0;
        int mhi = j; if (mhi > 511) mhi = 511;
        for (int m = mlo; m <= mhi; ++m) s += hp[m] * me[j - m];
    }
    g_hpme[j] = s;
}

// ---------------- prep_b: wlp + keff (launch 2) ----------------
__global__ void prep_b_kernel(const float* __restrict__ gt) {
    int j = threadIdx.x;
    if (j < 256) {
        double a = (double)(float)exp(-2.0 * M_PI * 2000.0 / 44100.0);
        double c = ((double)(j + 1) * (double)(j + 2) * (double)(j + 3) * (double)(j + 4)) / 24.0;
        double w = pow(1.0 - a, 5.0) * c * exp((double)j * log(a));
        g_wlp[j] = (float)w;
    }
    if (j < NCH) {
        const float* h = gt + j * LG;
        float mx = 0.f;
        for (int i = 0; i < LG; ++i) mx = fmaxf(mx, fabsf(h[i]));
        float thr = 1e-6f * mx;
        int last = 0;
        for (int i = 0; i < LG; ++i) if (fabsf(h[i]) > thr) last = i;
        int K = ((last + 1 + 7) / 8) * 8;
        if (K < 8) K = 8;
        if (K > LG) K = LG;
        g_keff[j] = K;
    }
}

// ---------------- conv0: x -> y1 (hp*me combined, 1024 taps) ----------------
__global__ __launch_bounds__(128) void conv0_kernel(const float* __restrict__ xin) {
    __shared__ __align__(16) float hr[1024];
    __shared__ __align__(16) float xs[1024 + 1024 + 16];

    int tid = threadIdx.x;
    int t0 = blockIdx.x * 1024;
    int row = blockIdx.y;
    const int K = 1024;

    const float* in = xin + (size_t)row * T_;
    float* out = g_y1 + (size_t)row * T_;

    for (int i = tid; i < K; i += 128) hr[i] = g_hpme[K - 1 - i];
    int xlen = K - 1 + 1024;
    for (int i = tid; i < xlen; i += 128) {
        int t = t0 - (K - 1) + i;
        xs[i] = (t >= 0 && t < T_) ? in[t] : 0.f;
    }
    __syncthreads();

    float acc[8];
#pragma unroll
    for (int r = 0; r < 8; ++r) acc[r] = 0.f;
    int off = tid * 8;

    for (int k = 0; k < K; k += 8) {
        float4 h0 = *reinterpret_cast<const float4*>(hr + k);
        float4 h1 = *reinterpret_cast<const float4*>(hr + k + 4);
        const float* xp = xs + off + k;
        float4 x0 = *reinterpret_cast<const float4*>(xp);
        float4 x1 = *reinterpret_cast<const float4*>(xp + 4);
        float4 x2 = *reinterpret_cast<const float4*>(xp + 8);
        float4 x3 = *reinterpret_cast<const float4*>(xp + 12);
        float hk[8] = {h0.x, h0.y, h0.z, h0.w, h1.x, h1.y, h1.z, h1.w};
        float xw[16] = {x0.x, x0.y, x0.z, x0.w, x1.x, x1.y, x1.z, x1.w,
                        x2.x, x2.y, x2.z, x2.w, x3.x, x3.y, x3.z, x3.w};
#pragma unroll
        for (int kk = 0; kk < 8; ++kk)
#pragma unroll
            for (int r = 0; r < 8; ++r)
                acc[r] = fmaf(hk[kk], xw[kk + r], acc[r]);
    }

#pragma unroll
    for (int r = 0; r < 8; ++r) {
        int t = t0 + off + r;
        if (t < T_) out[t] = acc[r];
    }
}

// ---------------- fused gammatone + rectify + IHC-LP conv v2 ----------------
__global__ __launch_bounds__(128) void conv_gt_ihc_kernel(const float* __restrict__ gtin) {
    __shared__ __align__(16) float hr[2048];
    __shared__ __align__(16) float wls[256];
    __shared__ __align__(16) float xs[2048 + CTILE + 256 + 16];
    __shared__ __align__(16) float hwS[CTILE + 256 + 16];

    int tid = threadIdx.x;
    int t0 = blockIdx.x * CTILE;
    int row = blockIdx.y;
    int b = row / NCH, n = row % NCH;

    const float* in = g_y1 + (size_t)b * T_;
    const float* gh = gtin + (size_t)n * LG;
    float* out = g_env + (size_t)row * EST;
    const int K = g_keff[n];

    for (int i = tid; i < K; i += 128) hr[i] = gh[K - 1 - i];
    for (int i = tid; i < 256; i += 128) wls[i] = g_wlp[255 - i];
    int tb = t0 - 255 - (K - 1);
    int xlen = K + CTILE + 256;
    for (int i = tid; i < xlen; i += 128) {
        int t = tb + i;
        xs[i] = (t >= 0 && t < T_) ? in[t] : 0.f;
    }
    __syncthreads();

    {
        float acc[16];
#pragma unroll
        for (int r = 0; r < 16; ++r) acc[r] = 0.f;
        int off = tid * 16;
        for (int k = 0; k < K; k += 8) {
            float4 h0 = *reinterpret_cast<const float4*>(hr + k);
            float4 h1 = *reinterpret_cast<const float4*>(hr + k + 4);
            const float* xp = xs + off + k;
            float4 x0 = *reinterpret_cast<const float4*>(xp);
            float4 x1 = *reinterpret_cast<const float4*>(xp + 4);
            float4 x2 = *reinterpret_cast<const float4*>(xp + 8);
            float4 x3 = *reinterpret_cast<const float4*>(xp + 12);
            float4 x4 = *reinterpret_cast<const float4*>(xp + 16);
            float4 x5 = *reinterpret_cast<const float4*>(xp + 20);
            float hk[8] = {h0.x, h0.y, h0.z, h0.w, h1.x, h1.y, h1.z, h1.w};
            float xw[24] = {x0.x, x0.y, x0.z, x0.w, x1.x, x1.y, x1.z, x1.w,
                            x2.x, x2.y, x2.z, x2.w, x3.x, x3.y, x3.z, x3.w,
                            x4.x, x4.y, x4.z, x4.w, x5.x, x5.y, x5.z, x5.w};
#pragma unroll
            for (int kk = 0; kk < 8; ++kk)
#pragma unroll
                for (int r = 0; r < 16; ++r)
                    acc[r] = fmaf(hk[kk], xw[kk + r], acc[r]);
        }
#pragma unroll
        for (int r = 0; r < 16; ++r) hwS[off + r] = fmaxf(acc[r], 0.f);
    }

    if (tid < 64) {
        float acc[4] = {0.f, 0.f, 0.f, 0.f};
        int off = CTILE + tid * 4;
        for (int k = 0; k < K; k += 8) {
            float4 h0 = *reinterpret_cast<const float4*>(hr + k);
            float4 h1 = *reinterpret_cast<const float4*>(hr + k + 4);
            const float* xp = xs + off + k;
            float4 x0 = *reinterpret_cast<const float4*>(xp);
            float4 x1 = *reinterpret_cast<const float4*>(xp + 4);
            float4 x2 = *reinterpret_cast<const float4*>(xp + 8);
            float hk[8] = {h0.x, h0.y, h0.z, h0.w, h1.x, h1.y, h1.z, h1.w};
            float xw[12] = {x0.x, x0.y, x0.z, x0.w, x1.x, x1.y, x1.z, x1.w,
                            x2.x, x2.y, x2.z, x2.w};
#pragma unroll
            for (int kk = 0; kk < 8; ++kk)
#pragma unroll
                for (int r = 0; r < 4; ++r)
                    acc[r] = fmaf(hk[kk], xw[kk + r], acc[r]);
        }
#pragma unroll
        for (int r = 0; r < 4; ++r) hwS[off + r] = fmaxf(acc[r], 0.f);
    }
    __syncthreads();

    {
        float acc[16];
#pragma unroll
        for (int r = 0; r < 16; ++r) acc[r] = 0.f;
        int off = tid * 16;
        for (int k = 0; k < 256; k += 8) {
            float4 h0 = *reinterpret_cast<const float4*>(wls + k);
            float4 h1 = *reinterpret_cast<const float4*>(wls + k + 4);
            const float* xp = hwS + off + k;
            float4 x0 = *reinterpret_cast<const float4*>(xp);
            float4 x1 = *reinterpret_cast<const float4*>(xp + 4);
            float4 x2 = *reinterpret_cast<const float4*>(xp + 8);
            float4 x3 = *reinterpret_cast<const float4*>(xp + 12);
            float4 x4 = *reinterpret_cast<const float4*>(xp + 16);
            float4 x5 = *reinterpret_cast<const float4*>(xp + 20);
            float hk[8] = {h0.x, h0.y, h0.z, h0.w, h1.x, h1.y, h1.z, h1.w};
            float xw[24] = {x0.x, x0.y, x0.z, x0.w, x1.x, x1.y, x1.z, x1.w,
                            x2.x, x2.y, x2.z, x2.w, x3.x, x3.y, x3.z, x3.w,
                            x4.x, x4.y, x4.z, x4.w, x5.x, x5.y, x5.z, x5.w};
#pragma unroll
            for (int kk = 0; kk < 8; ++kk)
#pragma unroll
                for (int r = 0; r < 16; ++r)
                    acc[r] = fmaf(hk[kk], xw[kk + r], acc[r]);
        }
        int tg = t0 + tid * 16;
#pragma unroll
        for (int q = 0; q < 4; ++q) {
            int t = tg + q * 4;
            if (t + 3 < T_) {
                *reinterpret_cast<float4*>(out + t) =
                    make_float4(acc[q*4+0], acc[q*4+1], acc[q*4+2], acc[q*4+3]);
            } else {
#pragma unroll
                for (int r = 0; r < 4; ++r)
                    if (t + r < T_) out[t + r] = acc[q*4 + r];
            }
        }
    }
}

// ---------------- adaptation: STAGE-PARALLEL systolic pipeline (v5) ----------------
// v5: 44-sample chunks (506 supersteps vs 694) to amortize barrier/coupling
// overhead; sbuf holds only stages 0-3 (stage 4 writes straight to gmem).
struct AD2 {
    float a1[5], b0[5], maxv[5], imaxv[5], ini[5];
    float minlvl, sc, sb;
};

__device__ __forceinline__ float rcpa(float x) {
    float r; asm("rcp.approx.f32 %0, %1;" : "=f"(r) : "f"(x)); return r;
}
__device__ __forceinline__ float rsqa(float x) {
    float r; asm("rsqrt.approx.f32 %0, %1;" : "=f"(r) : "f"(x)); return r;
}
__device__ __forceinline__ float tanha(float x) {
    float r; asm("tanh.approx.f32 %0, %1;" : "=f"(r) : "f"(x)); return r;
}

__global__ __launch_bounds__(160) void adapt_kernel(AD2 C) {
    __shared__ float sbuf[4][2][CHKS * 32];   // stages 0-3 only; 45 KB

    const int lane = threadIdx.x & 31;
    const int j = threadIdx.x >> 5;          // stage 0..4
    const bool act = (lane < NCH);
    const int c = blockIdx.x * NCH + (act ? lane : 0);
    const float* __restrict__ erow = g_env + (size_t)c * EST;
    float* __restrict__ arow = g_ad + (size_t)c * AST;

    const float a1 = C.a1[j], b0 = C.b0[j], mv = C.maxv[j];
    const float imv = C.imaxv[j], mimv = -C.imaxv[j];
    const float minlvl = C.minlvl, sc = C.sc, sb = C.sb;
    const bool isOut = (j == 4) && act;

    float st = C.ini[j];
    float rst = rcpa(st);        // exact seed; thereafter Newton-tracked
    float a1st = a1 * st;
    float twor = rst + rst;

    // warp 0: register double-buffer for env chunks (11 float4 per chunk)
    float4 pre4[11];
    if (j == 0) {
#pragma unroll
        for (int f = 0; f < 11; ++f)
            pre4[f] = *reinterpret_cast<const float4*>(erow + 4 * f);
    }

    for (int s = 0; s < NSS; ++s) {
        __syncthreads();
        int ck = s - j;
        if (ck >= 0 && ck < NCHK) {
            int ckb = ck * CHKS;
            float in[CHKS];
            if (j == 0) {
#pragma unroll
                for (int f = 0; f < 11; ++f) {
                    float4 v = pre4[f];
                    in[4*f+0] = fmaxf(v.x, minlvl);
                    in[4*f+1] = fmaxf(v.y, minlvl);
                    in[4*f+2] = fmaxf(v.z, minlvl);
                    in[4*f+3] = fmaxf(v.w, minlvl);
                }
                int nck = (ck + 1 < NCHK) ? (ck + 1) : 0;
                const float* nb = erow + nck * CHKS;
#pragma unroll
                for (int f = 0; f < 11; ++f)
                    pre4[f] = *reinterpret_cast<const float4*>(nb + 4 * f);
            } else {
                const float* src = sbuf[j - 1][(s - 1) & 1];
#pragma unroll
                for (int u = 0; u < CHKS; ++u) in[u] = src[u * 32 + lane];
            }
            float* dst = (j < 4) ? sbuf[j][s & 1] : 0;
            float o0 = 0.f, o1 = 0.f, o2 = 0.f;
#pragma unroll
            for (int u = 0; u < CHKS; ++u) {
                float t1  = in[u] * rst;
                float uu  = fmaf(t1, imv, mimv);
                float lim = fmaf(mv, tanha(uu), 1.0f);
                float tmp = fminf(t1, lim);
                st   = fmaf(b0, tmp, a1st);
                float e = st * rst;
                rst  = fmaf(rst, -e, twor);           // Newton: rst*(2 - st*rst)
                a1st = a1 * st;                       // off critical path
                twor = rst + rst;                     // off critical path
                if (j < 4) dst[u * 32 + lane] = tmp;
                float o = fmaf(tmp, sc, sb);
                if ((u & 3) == 3) {
                    int t0f = ckb + u - 3;
                    if (isOut && t0f <= 22048)        // float4 lands in row (AST pad absorbs tail)
                        *reinterpret_cast<float4*>(arow + t0f) = make_float4(o0, o1, o2, o);
                } else if ((u & 3) == 0) o0 = o;
                else if ((u & 3) == 1) o1 = o;
                else o2 = o;
            }
        }
    }
}

// ---------------- modulation filterbank: chunk-parallel linear IIR ----------------
struct MC2 {
    float pre[12], pim[12], pb0[12];
    float Are[12], Aim[12];   // pole^CL
    float att;
};

__global__ __launch_bounds__(128) void mod_pass1(MC2 C) {
    int idx = blockIdx.x * 128 + threadIdx.x;
    if (idx >= BNM * CH) return;
    int cm = idx % BNM;
    int k  = idx / BNM;
    int m = cm % M_, c = cm / M_;
    const float* __restrict__ arow = g_ad + (size_t)c * AST;
    const float pre = C.pre[m], pim = C.pim[m], pb0 = C.pb0[m];
    float sre = 0.f, sim = 0.f;
    if (k < CH - 1) {
        int t0 = k * CL, t1 = t0 + CL;
#pragma unroll 4
        for (int t = t0; t < t1; ++t) {
            float x = arow[t];
            float nre = fmaf(pre, sre, fmaf(-pim, sim, pb0 * x));
            float nim = fmaf(pre, sim, pim * sre);
            sre = nre; sim = nim;
        }
    }
    g_msre[idx] = sre; g_msim[idx] = sim;
}

__global__ __launch_bounds__(128) void mod_pass2(MC2 C) {
    int cm = blockIdx.x * 128 + threadIdx.x;
    if (cm >= BNM) return;
    int m = cm % M_;
    const float Are = C.Are[m], Aim = C.Aim[m];
    float Sre = 0.f, Sim = 0.f;
#pragma unroll
    for (int k = 0; k < CH; ++k) {
        int s = k * BNM + cm;
        g_Sre[s] = Sre; g_Sim[s] = Sim;
        float zre = g_msre[s], zim = g_msim[s];
        float nre = Are * Sre - Aim * Sim + zre;
        float nim = Are * Sim + Aim * Sre + zim;
        Sre = nre; Sim = nim;
    }
}

__global__ __launch_bounds__(128) void mod_pass3(float* __restrict__ out, MC2 C) {
    int idx = blockIdx.x * 128 + threadIdx.x;
    if (idx >= BNM * CH) return;
    int cm = idx % BNM;
    int k  = idx / BNM;
    int m = cm % M_, c = cm / M_;
    const float* __restrict__ arow = g_ad + (size_t)c * AST;
    float* __restrict__ orow = out + (size_t)cm * T_;
    const float pre = C.pre[m], pim = C.pim[m], pb0 = C.pb0[m];
    const float att = C.att;
    const bool low = (m < 3);
    int s = k * BNM + cm;
    float sre = g_Sre[s], sim = g_Sim[s];
    int t0 = k * CL;
    int t1 = t0 + CL; if (t1 > T_) t1 = T_;
#pragma unroll 4
    for (int t = t0; t < t1; ++t) {
        float x = arow[t];
        float nre = fmaf(pre, sre, fmaf(-pim, sim, pb0 * x));
        float nim = fmaf(pre, sim, pim * sre);
        sre = nre; sim = nim;
        float h = fmaf(nre, nre, fmaf(nim, nim, 1e-12f));
        orow[t] = low ? nre : att * h * rsqa(h);
    }
}

// ---------------- host launch ----------------
extern "C" void kernel_launch(void* const* d_in, const int* in_sizes, int n_in,
                              void* d_out, int out_size) {
    const float* x  = (const float*)d_in[0];
    const float* hp = (const float*)d_in[1];
    const float* me = (const float*)d_in[2];
    const float* gt = (const float*)d_in[3];
    float* out = (float*)d_out;
    (void)in_sizes; (void)n_in; (void)out_size;

    AD2 A;
    const double taus[5] = {0.005, 0.05, 0.129, 0.253, 0.5};
    for (int j = 0; j < 5; ++j) {
        double a1d = exp(-1.0 / (44100.0 * taus[j]));
        float a1f = (float)a1d;
        A.a1[j] = a1f;
        A.b0[j] = 1.0f - a1f;
        double ini = pow(1e-5, pow(2.0, -(double)(j + 1)));
        float inif = (float)ini;
        A.ini[j] = inif;
        double maxv = (1.0 - (double)inif * (double)inif) * 5.0 - 1.0;
        A.maxv[j]  = (float)maxv;      // limited == 1 + maxv*tanh((t-1)/maxv)
        A.imaxv[j] = (float)(1.0 / maxv);
    }
    double corr = pow(1e-5, 1.0 / 32.0);
    double scale = 100.0 / (1.0 - corr);
    A.minlvl = 1e-5f;
    A.sc = (float)scale;
    A.sb = (float)(-corr * scale);

    MC2 Mc;
    const float mfcf[12] = {2.5f, 5.0f, 10.0f, 16.7f, 27.8f, 46.3f, 77.2f,
                            128.6f, 214.3f, 357.2f, 595.4f, 992.3f};
    for (int m = 0; m < 12; ++m) {
        double mv = (double)mfcf[m];
        double r  = exp(-M_PI * (mv / 2.0) / 44100.0);
        double th = 2.0 * M_PI * mv / 44100.0;
        Mc.pre[m] = (float)(r * cos(th));
        Mc.pim[m] = (float)(r * sin(th));
        Mc.pb0[m] = (float)(1.0 - r);
        double pr = (double)Mc.pre[m], pi = (double)Mc.pim[m];
        double ar = 1.0, ai = 0.0;
        for (int i = 0; i < CL; ++i) {
            double nr = ar * pr - ai * pi;
            ai = ar * pi + ai * pr;
            ar = nr;
        }
        Mc.Are[m] = (float)ar;
        Mc.Aim[m] = (float)ai;
    }
    Mc.att = (float)(1.0 / sqrt(2.0));

    // ncu capture grabs launch index 3 -> conv_gt_ihc is profiled this round.
    prep_a_kernel<<<1, 1024>>>(hp, me);                         // 0
    conv0_kernel<<<dim3(22, B_), 128>>>(x);                     // 1
    prep_b_kernel<<<1, 256>>>(gt);                              // 2
    conv_gt_ihc_kernel<<<dim3(11, BN), 128>>>(gt);              // 3 <- profiled
    adapt_kernel<<<B_, 160>>>(A);                               // 4
    mod_pass1<<<(BNM * CH + 127) / 128, 128>>>(Mc);             // 5
    mod_pass2<<<(BNM + 127) / 128, 128>>>(Mc);                  // 6
    mod_pass3<<<(BNM * CH + 127) / 128, 128>>>(out, Mc);        // 7
}

// round 17
// speedup vs baseline: 1.1722x; 1.1722x over previous
#include <cuda_runtime.h>
#include <math.h>

#define B_   8
#define T_   22050
#define NCH  31
#define BN   (B_*NCH)
#define M_   12
#define LG   2048
#define LH   512
#define EST  22056   // padded env row stride (floats); 16B-aligned rows
#define AST  22052   // padded adapt-out row stride; 16B-aligned rows
#define CH   8       // mod time chunks
#define CL   2757    // chunk length (8*2757 >= T_)
#define BNM  (BN*M_)
#define CTILE 2048   // conv_gt_ihc outputs per block
#define NCHK 690     // adapt: ceil(22050/32)
#define NSS  (NCHK + 4)

// ---------------- device scratch (static, no runtime alloc) ----------------
__device__ float g_hpme[1024];
__device__ float g_wlp[256];
__device__ int   g_keff[NCH];
__device__ float g_y1[B_*T_];
__device__ __align__(16) float g_env[BN*EST + 64];
__device__ __align__(16) float g_ad[BN*AST + 64];
__device__ float g_msre[BNM*CH], g_msim[BNM*CH];
__device__ float g_Sre[BNM*CH],  g_Sim[BNM*CH];

// ---------------- prep_a: hpme only (launch 0) ----------------
__global__ void prep_a_kernel(const float* __restrict__ hp, const float* __restrict__ me) {
    int j = threadIdx.x;
    float s = 0.f;
    if (j < 1023) {
        int mlo = j - 511; if (mlo < 0) mlo = 0;
        int mhi = j; if (mhi > 511) mhi = 511;
        for (int m = mlo; m <= mhi; ++m) s += hp[m] * me[j - m];
    }
    g_hpme[j] = s;
}

// ---------------- prep_b: wlp + keff (launch 2) ----------------
__global__ void prep_b_kernel(const float* __restrict__ gt) {
    int j = threadIdx.x;
    if (j < 256) {
        double a = (double)(float)exp(-2.0 * M_PI * 2000.0 / 44100.0);
        double c = ((double)(j + 1) * (double)(j + 2) * (double)(j + 3) * (double)(j + 4)) / 24.0;
        double w = pow(1.0 - a, 5.0) * c * exp((double)j * log(a));
        g_wlp[j] = (float)w;
    }
    if (j < NCH) {
        const float* h = gt + j * LG;
        float mx = 0.f;
        for (int i = 0; i < LG; ++i) mx = fmaxf(mx, fabsf(h[i]));
        float thr = 1e-6f * mx;
        int last = 0;
        for (int i = 0; i < LG; ++i) if (fabsf(h[i]) > thr) last = i;
        int K = ((last + 1 + 7) / 8) * 8;
        if (K < 8) K = 8;
        if (K > LG) K = LG;
        g_keff[j] = K;
    }
}

// ---------------- conv0: x -> y1 (hp*me combined, 1024 taps) ----------------
__global__ __launch_bounds__(128) void conv0_kernel(const float* __restrict__ xin) {
    __shared__ __align__(16) float hr[1024];
    __shared__ __align__(16) float xs[1024 + 1024 + 16];

    int tid = threadIdx.x;
    int t0 = blockIdx.x * 1024;
    int row = blockIdx.y;
    const int K = 1024;

    const float* in = xin + (size_t)row * T_;
    float* out = g_y1 + (size_t)row * T_;

    for (int i = tid; i < K; i += 128) hr[i] = g_hpme[K - 1 - i];
    int xlen = K - 1 + 1024;
    for (int i = tid; i < xlen; i += 128) {
        int t = t0 - (K - 1) + i;
        xs[i] = (t >= 0 && t < T_) ? in[t] : 0.f;
    }
    __syncthreads();

    float acc[8];
#pragma unroll
    for (int r = 0; r < 8; ++r) acc[r] = 0.f;
    int off = tid * 8;

    for (int k = 0; k < K; k += 8) {
        float4 h0 = *reinterpret_cast<const float4*>(hr + k);
        float4 h1 = *reinterpret_cast<const float4*>(hr + k + 4);
        const float* xp = xs + off + k;
        float4 x0 = *reinterpret_cast<const float4*>(xp);
        float4 x1 = *reinterpret_cast<const float4*>(xp + 4);
        float4 x2 = *reinterpret_cast<const float4*>(xp + 8);
        float4 x3 = *reinterpret_cast<const float4*>(xp + 12);
        float hk[8] = {h0.x, h0.y, h0.z, h0.w, h1.x, h1.y, h1.z, h1.w};
        float xw[16] = {x0.x, x0.y, x0.z, x0.w, x1.x, x1.y, x1.z, x1.w,
                        x2.x, x2.y, x2.z, x2.w, x3.x, x3.y, x3.z, x3.w};
#pragma unroll
        for (int kk = 0; kk < 8; ++kk)
#pragma unroll
            for (int r = 0; r < 8; ++r)
                acc[r] = fmaf(hk[kk], xw[kk + r], acc[r]);
    }

#pragma unroll
    for (int r = 0; r < 8; ++r) {
        int t = t0 + off + r;
        if (t < T_) out[t] = acc[r];
    }
}

// ---------------- rolling-window 8-tap FIR micro-step ----------------
template<int BASE>
__device__ __forceinline__ void fir8(const float4 h0, const float4 h1,
                                     const float (&w)[24], float (&acc)[16]) {
    float hk[8] = {h0.x, h0.y, h0.z, h0.w, h1.x, h1.y, h1.z, h1.w};
#pragma unroll
    for (int kk = 0; kk < 8; ++kk)
#pragma unroll
        for (int r = 0; r < 16; ++r)
            acc[r] = fmaf(hk[kk], w[(BASE + kk + r) % 24], acc[r]);
}

// ---------------- fused gammatone + rectify + IHC-LP conv v3 ----------------
// Rolling 24-float register window: 2 LDS.128 of new data per 8 taps (3x less
// smem traffic than v2). Taps zero-padded to multiples of 24 (bit-identical).
__global__ __launch_bounds__(128) void conv_gt_ihc_kernel(const float* __restrict__ gtin) {
    __shared__ __align__(16) float hr[2064 + 16];
    __shared__ __align__(16) float wls[264 + 8];
    __shared__ __align__(16) float xs[2064 + CTILE + 256 + 32];
    __shared__ __align__(16) float hwS[CTILE + 256 + 16];

    int tid = threadIdx.x;
    int t0 = blockIdx.x * CTILE;
    int row = blockIdx.y;
    int b = row / NCH, n = row % NCH;

    const float* in = g_y1 + (size_t)b * T_;
    const float* gh = gtin + (size_t)n * LG;
    float* out = g_env + (size_t)row * EST;
    const int K = g_keff[n];
    const int K24 = ((K + 23) / 24) * 24;     // <= 2064

    for (int i = tid; i < K24; i += 128) hr[i] = (i < K) ? gh[K - 1 - i] : 0.f;
    for (int i = tid; i < 264; i += 128) wls[i] = (i < 256) ? g_wlp[255 - i] : 0.f;
    int tb = t0 - 255 - (K - 1);                 // xs[i] = y1[tb+i]
    int xlen = K24 + CTILE + 256 + 24;
    for (int i = tid; i < xlen; i += 128) {
        int t = tb + i;
        xs[i] = (t >= 0 && t < T_) ? in[t] : 0.f;
    }
    __syncthreads();

    // ---- pass 1a: gammatone, 16 outputs/thread, rolling window ----
    {
        float acc[16];
#pragma unroll
        for (int r = 0; r < 16; ++r) acc[r] = 0.f;
        const float* xp0 = xs + tid * 16;
        float w[24];
#pragma unroll
        for (int f = 0; f < 4; ++f) {
            float4 v = *reinterpret_cast<const float4*>(xp0 + 4 * f);
            w[4*f+0] = v.x; w[4*f+1] = v.y; w[4*f+2] = v.z; w[4*f+3] = v.w;
        }
        for (int k = 0; k < K24; k += 24) {
            {   // taps k..k+7 (window base 0); bring in w[16..23]
                float4 a = *reinterpret_cast<const float4*>(xp0 + k + 16);
                float4 bv = *reinterpret_cast<const float4*>(xp0 + k + 20);
                w[16]=a.x; w[17]=a.y; w[18]=a.z; w[19]=a.w;
                w[20]=bv.x; w[21]=bv.y; w[22]=bv.z; w[23]=bv.w;
                float4 h0 = *reinterpret_cast<const float4*>(hr + k);
                float4 h1 = *reinterpret_cast<const float4*>(hr + k + 4);
                fir8<0>(h0, h1, w, acc);
            }
            {   // taps k+8..k+15 (base 8); bring in w[0..7]
                float4 a = *reinterpret_cast<const float4*>(xp0 + k + 24);
                float4 bv = *reinterpret_cast<const float4*>(xp0 + k + 28);
                w[0]=a.x; w[1]=a.y; w[2]=a.z; w[3]=a.w;
                w[4]=bv.x; w[5]=bv.y; w[6]=bv.z; w[7]=bv.w;
                float4 h0 = *reinterpret_cast<const float4*>(hr + k + 8);
                float4 h1 = *reinterpret_cast<const float4*>(hr + k + 12);
                fir8<8>(h0, h1, w, acc);
            }
            {   // taps k+16..k+23 (base 16); bring in w[8..15]
                float4 a = *reinterpret_cast<const float4*>(xp0 + k + 32);
                float4 bv = *reinterpret_cast<const float4*>(xp0 + k + 36);
                w[8]=a.x; w[9]=a.y; w[10]=a.z; w[11]=a.w;
                w[12]=bv.x; w[13]=bv.y; w[14]=bv.z; w[15]=bv.w;
                float4 h0 = *reinterpret_cast<const float4*>(hr + k + 16);
                float4 h1 = *reinterpret_cast<const float4*>(hr + k + 20);
                fir8<16>(h0, h1, w, acc);
            }
        }
        int off = tid * 16;
#pragma unroll
        for (int r = 0; r < 16; ++r) hwS[off + r] = fmaxf(acc[r], 0.f);
    }

    // ---- pass 1b: halo (hwS idx 2048..2303): 64 threads x 4 outputs ----
    if (tid < 64) {
        float acc[4] = {0.f, 0.f, 0.f, 0.f};
        int off = CTILE + tid * 4;
        for (int k = 0; k < K; k += 8) {
            float4 h0 = *reinterpret_cast<const float4*>(hr + k);
            float4 h1 = *reinterpret_cast<const float4*>(hr + k + 4);
            const float* xp = xs + off + k;
            float4 x0 = *reinterpret_cast<const float4*>(xp);
            float4 x1 = *reinterpret_cast<const float4*>(xp + 4);
            float4 x2 = *reinterpret_cast<const float4*>(xp + 8);
            float hk[8] = {h0.x, h0.y, h0.z, h0.w, h1.x, h1.y, h1.z, h1.w};
            float xw[12] = {x0.x, x0.y, x0.z, x0.w, x1.x, x1.y, x1.z, x1.w,
                            x2.x, x2.y, x2.z, x2.w};
#pragma unroll
            for (int kk = 0; kk < 8; ++kk)
#pragma unroll
                for (int r = 0; r < 4; ++r)
                    acc[r] = fmaf(hk[kk], xw[kk + r], acc[r]);
        }
#pragma unroll
        for (int r = 0; r < 4; ++r) hwS[off + r] = fmaxf(acc[r], 0.f);
    }
    __syncthreads();

    // ---- pass 2: IHC FIR (264 taps incl. 8 zero pads), rolling window ----
    {
        float acc[16];
#pragma unroll
        for (int r = 0; r < 16; ++r) acc[r] = 0.f;
        const float* xp0 = hwS + tid * 16;
        float w[24];
#pragma unroll
        for (int f = 0; f < 4; ++f) {
            float4 v = *reinterpret_cast<const float4*>(xp0 + 4 * f);
            w[4*f+0] = v.x; w[4*f+1] = v.y; w[4*f+2] = v.z; w[4*f+3] = v.w;
        }
#pragma unroll
        for (int k = 0; k < 264; k += 24) {
            {
                float4 a = *reinterpret_cast<const float4*>(xp0 + k + 16);
                float4 bv = *reinterpret_cast<const float4*>(xp0 + k + 20);
                w[16]=a.x; w[17]=a.y; w[18]=a.z; w[19]=a.w;
                w[20]=bv.x; w[21]=bv.y; w[22]=bv.z; w[23]=bv.w;
                float4 h0 = *reinterpret_cast<const float4*>(wls + k);
                float4 h1 = *reinterpret_cast<const float4*>(wls + k + 4);
                fir8<0>(h0, h1, w, acc);
            }
            {
                float4 a = *reinterpret_cast<const float4*>(xp0 + k + 24);
                float4 bv = *reinterpret_cast<const float4*>(xp0 + k + 28);
                w[0]=a.x; w[1]=a.y; w[2]=a.z; w[3]=a.w;
                w[4]=bv.x; w[5]=bv.y; w[6]=bv.z; w[7]=bv.w;
                float4 h0 = *reinterpret_cast<const float4*>(wls + k + 8);
                float4 h1 = *reinterpret_cast<const float4*>(wls + k + 12);
                fir8<8>(h0, h1, w, acc);
            }
            {
                float4 a = *reinterpret_cast<const float4*>(xp0 + k + 32);
                float4 bv = *reinterpret_cast<const float4*>(xp0 + k + 36);
                w[8]=a.x; w[9]=a.y; w[10]=a.z; w[11]=a.w;
                w[12]=bv.x; w[13]=bv.y; w[14]=bv.z; w[15]=bv.w;
                float4 h0 = *reinterpret_cast<const float4*>(wls + k + 16);
                float4 h1 = *reinterpret_cast<const float4*>(wls + k + 20);
                fir8<16>(h0, h1, w, acc);
            }
        }
        int tg = t0 + tid * 16;
#pragma unroll
        for (int q = 0; q < 4; ++q) {
            int t = tg + q * 4;
            if (t + 3 < T_) {
                *reinterpret_cast<float4*>(out + t) =
                    make_float4(acc[q*4+0], acc[q*4+1], acc[q*4+2], acc[q*4+3]);
            } else {
#pragma unroll
                for (int r = 0; r < 4; ++r)
                    if (t + r < T_) out[t + r] = acc[q*4 + r];
            }
        }
    }
}

// ---------------- adaptation: STAGE-PARALLEL systolic pipeline (R15 version) ----------------
struct AD2 {
    float a1[5], b0[5], maxv[5], imaxv[5], ini[5];
    float minlvl, sc, sb;
};

__device__ __forceinline__ float rcpa(float x) {
    float r; asm("rcp.approx.f32 %0, %1;" : "=f"(r) : "f"(x)); return r;
}
__device__ __forceinline__ float rsqa(float x) {
    float r; asm("rsqrt.approx.f32 %0, %1;" : "=f"(r) : "f"(x)); return r;
}
__device__ __forceinline__ float tanha(float x) {
    float r; asm("tanh.approx.f32 %0, %1;" : "=f"(r) : "f"(x)); return r;
}

__global__ __launch_bounds__(160) void adapt_kernel(AD2 C) {
    __shared__ float sbuf[5][2][32 * 32];

    const int lane = threadIdx.x & 31;
    const int j = threadIdx.x >> 5;
    const bool act = (lane < NCH);
    const int c = blockIdx.x * NCH + (act ? lane : 0);
    const float* __restrict__ erow = g_env + (size_t)c * EST;
    float* __restrict__ arow = g_ad + (size_t)c * AST;

    const float a1 = C.a1[j], b0 = C.b0[j], mv = C.maxv[j];
    const float imv = C.imaxv[j], mimv = -C.imaxv[j];
    const float minlvl = C.minlvl, sc = C.sc, sb = C.sb;
    const bool isOut = (j == 4) && act;

    float st = C.ini[j];
    float rst = rcpa(st);
    float a1st = a1 * st;
    float twor = rst + rst;

    float4 pre4[8];
    if (j == 0) {
#pragma unroll
        for (int f = 0; f < 8; ++f)
            pre4[f] = *reinterpret_cast<const float4*>(erow + 4 * f);
    }

    for (int s = 0; s < NSS; ++s) {
        __syncthreads();
        int ck = s - j;
        if (ck >= 0 && ck < NCHK) {
            int ckb = ck * 32;
            float in[32];
            if (j == 0) {
#pragma unroll
                for (int f = 0; f < 8; ++f) {
                    float4 v = pre4[f];
                    in[4*f+0] = fmaxf(v.x, minlvl);
                    in[4*f+1] = fmaxf(v.y, minlvl);
                    in[4*f+2] = fmaxf(v.z, minlvl);
                    in[4*f+3] = fmaxf(v.w, minlvl);
                }
                int nck = (ck + 1 < NCHK) ? (ck + 1) : 0;
                const float* nb = erow + nck * 32;
#pragma unroll
                for (int f = 0; f < 8; ++f)
                    pre4[f] = *reinterpret_cast<const float4*>(nb + 4 * f);
            } else {
                const float* src = sbuf[j - 1][(s - 1) & 1];
#pragma unroll
                for (int u = 0; u < 32; ++u) in[u] = src[u * 32 + lane];
            }
            float* dst = sbuf[j][s & 1];
            float o0 = 0.f, o1 = 0.f, o2 = 0.f;
#pragma unroll
            for (int u = 0; u < 32; ++u) {
                float t1  = in[u] * rst;
                float uu  = fmaf(t1, imv, mimv);
                float lim = fmaf(mv, tanha(uu), 1.0f);
                float tmp = fminf(t1, lim);
                st   = fmaf(b0, tmp, a1st);
                float e = st * rst;
                rst  = fmaf(rst, -e, twor);
                a1st = a1 * st;
                twor = rst + rst;
                if (j < 4) dst[u * 32 + lane] = tmp;
                float o = fmaf(tmp, sc, sb);
                if ((u & 3) == 3) {
                    int t0f = ckb + u - 3;
                    if (isOut && t0f <= 22048)
                        *reinterpret_cast<float4*>(arow + t0f) = make_float4(o0, o1, o2, o);
                } else if ((u & 3) == 0) o0 = o;
                else if ((u & 3) == 1) o1 = o;
                else o2 = o;
            }
        }
    }
}

// ---------------- modulation filterbank: chunk-parallel linear IIR ----------------
struct MC2 {
    float pre[12], pim[12], pb0[12];
    float Are[12], Aim[12];
    float att;
};

__global__ __launch_bounds__(128) void mod_pass1(MC2 C) {
    int idx = blockIdx.x * 128 + threadIdx.x;
    if (idx >= BNM * CH) return;
    int cm = idx % BNM;
    int k  = idx / BNM;
    int m = cm % M_, c = cm / M_;
    const float* __restrict__ arow = g_ad + (size_t)c * AST;
    const float pre = C.pre[m], pim = C.pim[m], pb0 = C.pb0[m];
    float sre = 0.f, sim = 0.f;
    if (k < CH - 1) {
        int t0 = k * CL, t1 = t0 + CL;
#pragma unroll 4
        for (int t = t0; t < t1; ++t) {
            float x = arow[t];
            float nre = fmaf(pre, sre, fmaf(-pim, sim, pb0 * x));
            float nim = fmaf(pre, sim, pim * sre);
            sre = nre; sim = nim;
        }
    }
    g_msre[idx] = sre; g_msim[idx] = sim;
}

__global__ __launch_bounds__(128) void mod_pass2(MC2 C) {
    int cm = blockIdx.x * 128 + threadIdx.x;
    if (cm >= BNM) return;
    int m = cm % M_;
    const float Are = C.Are[m], Aim = C.Aim[m];
    float Sre = 0.f, Sim = 0.f;
#pragma unroll
    for (int k = 0; k < CH; ++k) {
        int s = k * BNM + cm;
        g_Sre[s] = Sre; g_Sim[s] = Sim;
        float zre = g_msre[s], zim = g_msim[s];
        float nre = Are * Sre - Aim * Sim + zre;
        float nim = Are * Sim + Aim * Sre + zim;
        Sre = nre; Sim = nim;
    }
}

__global__ __launch_bounds__(128) void mod_pass3(float* __restrict__ out, MC2 C) {
    int idx = blockIdx.x * 128 + threadIdx.x;
    if (idx >= BNM * CH) return;
    int cm = idx % BNM;
    int k  = idx / BNM;
    int m = cm % M_, c = cm / M_;
    const float* __restrict__ arow = g_ad + (size_t)c * AST;
    float* __restrict__ orow = out + (size_t)cm * T_;
    const float pre = C.pre[m], pim = C.pim[m], pb0 = C.pb0[m];
    const float att = C.att;
    const bool low = (m < 3);
    int s = k * BNM + cm;
    float sre = g_Sre[s], sim = g_Sim[s];
    int t0 = k * CL;
    int t1 = t0 + CL; if (t1 > T_) t1 = T_;
#pragma unroll 4
    for (int t = t0; t < t1; ++t) {
        float x = arow[t];
        float nre = fmaf(pre, sre, fmaf(-pim, sim, pb0 * x));
        float nim = fmaf(pre, sim, pim * sre);
        sre = nre; sim = nim;
        float h = fmaf(nre, nre, fmaf(nim, nim, 1e-12f));
        orow[t] = low ? nre : att * h * rsqa(h);
    }
}

// ---------------- host launch ----------------
extern "C" void kernel_launch(void* const* d_in, const int* in_sizes, int n_in,
                              void* d_out, int out_size) {
    const float* x  = (const float*)d_in[0];
    const float* hp = (const float*)d_in[1];
    const float* me = (const float*)d_in[2];
    const float* gt = (const float*)d_in[3];
    float* out = (float*)d_out;
    (void)in_sizes; (void)n_in; (void)out_size;

    AD2 A;
    const double taus[5] = {0.005, 0.05, 0.129, 0.253, 0.5};
    for (int j = 0; j < 5; ++j) {
        double a1d = exp(-1.0 / (44100.0 * taus[j]));
        float a1f = (float)a1d;
        A.a1[j] = a1f;
        A.b0[j] = 1.0f - a1f;
        double ini = pow(1e-5, pow(2.0, -(double)(j + 1)));
        float inif = (float)ini;
        A.ini[j] = inif;
        double maxv = (1.0 - (double)inif * (double)inif) * 5.0 - 1.0;
        A.maxv[j]  = (float)maxv;
        A.imaxv[j] = (float)(1.0 / maxv);
    }
    double corr = pow(1e-5, 1.0 / 32.0);
    double scale = 100.0 / (1.0 - corr);
    A.minlvl = 1e-5f;
    A.sc = (float)scale;
    A.sb = (float)(-corr * scale);

    MC2 Mc;
    const float mfcf[12] = {2.5f, 5.0f, 10.0f, 16.7f, 27.8f, 46.3f, 77.2f,
                            128.6f, 214.3f, 357.2f, 595.4f, 992.3f};
    for (int m = 0; m < 12; ++m) {
        double mv = (double)mfcf[m];
        double r  = exp(-M_PI * (mv / 2.0) / 44100.0);
        double th = 2.0 * M_PI * mv / 44100.0;
        Mc.pre[m] = (float)(r * cos(th));
        Mc.pim[m] = (float)(r * sin(th));
        Mc.pb0[m] = (float)(1.0 - r);
        double pr = (double)Mc.pre[m], pi = (double)Mc.pim[m];
        double ar = 1.0, ai = 0.0;
        for (int i = 0; i < CL; ++i) {
            double nr = ar * pr - ai * pi;
            ai = ar * pi + ai * pr;
            ar = nr;
        }
        Mc.Are[m] = (float)ar;
        Mc.Aim[m] = (float)ai;
    }
    Mc.att = (float)(1.0 / sqrt(2.0));

    // ncu capture grabs launch index 3 -> conv_gt_ihc stays profiled.
    prep_a_kernel<<<1, 1024>>>(hp, me);                         // 0
    conv0_kernel<<<dim3(22, B_), 128>>>(x);                     // 1
    prep_b_kernel<<<1, 256>>>(gt);                              // 2
    conv_gt_ihc_kernel<<<dim3(11, BN), 128>>>(gt);              // 3 <- profiled
    adapt_kernel<<<B_, 160>>>(A);                               // 4
    mod_pass1<<<(BNM * CH + 127) / 128, 128>>>(Mc);             // 5
    mod_pass2<<<(BNM + 127) / 128, 128>>>(Mc);                  // 6
    mod_pass3<<<(BNM * CH + 127) / 128, 128>>>(out, Mc);        // 7
}